// round 12
// baseline (speedup 1.0000x reference)
#include <cuda_runtime.h>
#include <cuda_fp16.h>
#include <mma.h>
#include <math.h>

using namespace nvcuda;

#define NBAG 512
#define MS 8
#define TT 64
#define BDIM 4096          // NBAG*MS
#define INDIM 360
#define HH 230
#define H2 460
#define G3 690
#define G3P 768            // xg row stride
#define NOUT 53
#define NDOCS 32
#define NENT 8
#define HP 232             // fp32 h row stride
#define HPH 256            // fp16 h row stride / Whh k,j pad
#define KXP 384            // input K pad (360 data + ones@360 + 0s)
#define NXP 768            // Wih n pad (= G3P, unguarded tiles)
#define WKP 512            // word K pad (256 + 256)
#define WNP 464            // word n pad
#define M_TOT (BDIM * TT)  // 262144
#define GRU_BLOCKS 256     // persistent kernel grid (all co-resident: 256 <= 148*2)

// ------------------- scratch (device globals; zero-initialized at module load) -------------------
__device__ __align__(256) __half g_xh[(size_t)M_TOT * KXP];          // bag fp16, m' = t*BDIM+b
__device__ __align__(256) __half g_Wih[2ull * KXP * NXP];            // [dir][k][n], bias at k=360
__device__ __align__(256) __half g_xg[2ull * M_TOT * G3P];           // [dir][t][b][768]
__device__ __align__(256) __half g_Whh[2ull * 3 * HPH * HPH];        // [dir][g][k][j]
__device__ __align__(256) __half g_Ww[(size_t)WKP * WNP];            // word W, k-gap baked
__device__ float g_hf[(size_t)(TT + 1) * BDIM * HP];                 // fp32 h (blend)
__device__ float g_hr[(size_t)(TT + 1) * BDIM * HP];
__device__ __align__(256) __half g_hfh[(size_t)(TT + 1) * BDIM * HPH];  // fp16 h (MMA/attn)
__device__ __align__(256) __half g_hrh[(size_t)(TT + 1) * BDIM * HPH];
__device__ float g_scores[(size_t)BDIM * TT];
__device__ float g_wordvec[(size_t)BDIM * H2];
__device__ unsigned g_barC;   // grid barrier count (self-resets each run)
__device__ unsigned g_barG;   // grid barrier generation (monotonic; relative compare)

#define H16(x) __float2half(x)

// =================== prep kernels ===================
__global__ void conv_x(const float* __restrict__ bag)
{
    size_t idx = (size_t)blockIdx.x * 256 + threadIdx.x;
    const size_t total = (size_t)M_TOT * 46;
    if (idx >= total) return;
    size_t m = idx / 46;
    int kc = (int)(idx % 46) * 8;
    int t = (int)(m >> 12), b = (int)(m & (BDIM - 1));
    __half out[8];
    if (kc < INDIM) {
        const float* src = bag + ((size_t)b * TT + t) * INDIM + kc;
        float4 v0 = *(const float4*)src;
        float4 v1 = *(const float4*)(src + 4);
        out[0] = H16(v0.x); out[1] = H16(v0.y); out[2] = H16(v0.z); out[3] = H16(v0.w);
        out[4] = H16(v1.x); out[5] = H16(v1.y); out[6] = H16(v1.z); out[7] = H16(v1.w);
    } else {   // kc == 360: ones column for bias folding, then zeros
        out[0] = H16(1.f);
        #pragma unroll
        for (int q = 1; q < 8; q++) out[q] = H16(0.f);
    }
    *(uint4*)&g_xh[m * KXP + kc] = *(uint4*)out;
}

__global__ void conv_wih(const float* __restrict__ Wf, const float* __restrict__ bf_,
                         const float* __restrict__ Wr, const float* __restrict__ br_)
{
    int idx = blockIdx.x * 256 + threadIdx.x;
    const int per = 361 * G3;
    if (idx >= 2 * per) return;
    int dir = idx / per, r = idx % per;
    int k = r / G3, n = r % G3;
    const float* W = dir ? Wr : Wf;
    const float* bias = dir ? br_ : bf_;
    float v = (k < INDIM) ? W[(size_t)n * INDIM + k] : bias[n];
    g_Wih[((size_t)dir * KXP + k) * NXP + n] = H16(v);
}

__global__ void conv_whh(const float* __restrict__ Wf, const float* __restrict__ Wr)
{
    int idx = blockIdx.x * 256 + threadIdx.x;
    const int per = 3 * HH * HH;
    if (idx >= 2 * per) return;
    int dir = idx / per, r = idx % per;
    int g = r / (HH * HH); r %= HH * HH;
    int k = r / HH, j = r % HH;
    const float* W = dir ? Wr : Wf;
    g_Whh[(((size_t)dir * 3 + g) * HPH + k) * HPH + j] = H16(W[(size_t)(g * HH + j) * HH + k]);
}

__global__ void conv_ww(const float* __restrict__ Ww)
{
    int idx = blockIdx.x * 256 + threadIdx.x;
    if (idx >= WKP * H2) return;
    int kp = idx / H2, j = idx % H2;
    int ksrc = (kp < HH) ? kp : ((kp >= HPH && kp < HPH + HH) ? (kp - (HPH - HH)) : -1);
    if (ksrc >= 0)
        g_Ww[(size_t)kp * WNP + j] = H16(Ww[(size_t)ksrc * H2 + j]);
}

// =================== 1. input GEMM: xg = xh @ Wih (bias via ones-column) ===================
// M=262144, N=768 (6 tiles of 128), K=384 (12 slabs of 32). 8 warps 4x2, warp 32x64.
__global__ __launch_bounds__(256) void input_gemm3()
{
    __shared__ __half sA[2][128 * 40];
    __shared__ __half sB[2][32 * 136];
    __shared__ float  sC[8 * 256];

    const int dir = blockIdx.z;
    const __half* Wh = g_Wih + (size_t)dir * KXP * NXP;
    __half* C = g_xg + (size_t)dir * M_TOT * G3P;

    const int n0 = blockIdx.x * 128;
    const int mt0 = blockIdx.y * 128;
    const int tid = threadIdx.x;
    const int warp = tid >> 5, lane = tid & 31;
    const int wm = warp >> 1, wn = warp & 1;

    wmma::fragment<wmma::accumulator, 16, 16, 16, float> acc[2][4];
    #pragma unroll
    for (int i = 0; i < 2; i++)
        #pragma unroll
        for (int j = 0; j < 4; j++) wmma::fill_fragment(acc[i][j], 0.f);

    const int am = tid >> 1, ak = (tid & 1) * 16;
    const __half* ap = g_xh + (size_t)(mt0 + am) * KXP + ak;
    const int bkr = tid >> 3, bch = (tid & 7) * 16;
    const __half* bp = Wh + (size_t)bkr * NXP + n0 + bch;

    uint4 aR0 = *(const uint4*)ap;
    uint4 aR1 = *(const uint4*)(ap + 8);
    uint4 bR0 = *(const uint4*)bp;
    uint4 bR1 = *(const uint4*)(bp + 8);

    const int NIT = KXP / 32;  // 12
    *(uint4*)&sA[0][am * 40 + ak]     = aR0;
    *(uint4*)&sA[0][am * 40 + ak + 8] = aR1;
    *(uint4*)&sB[0][bkr * 136 + bch]     = bR0;
    *(uint4*)&sB[0][bkr * 136 + bch + 8] = bR1;
    __syncthreads();

    for (int it = 0; it < NIT; ++it) {
        const int cur = it & 1;
        if (it + 1 < NIT) {
            int k0 = (it + 1) * 32;
            aR0 = *(const uint4*)(ap + k0);
            aR1 = *(const uint4*)(ap + k0 + 8);
            bR0 = *(const uint4*)(bp + (size_t)k0 * NXP);
            bR1 = *(const uint4*)(bp + (size_t)k0 * NXP + 8);
        }
        #pragma unroll
        for (int ks = 0; ks < 32; ks += 16) {
            wmma::fragment<wmma::matrix_a, 16, 16, 16, __half, wmma::row_major> af[2];
            #pragma unroll
            for (int mi = 0; mi < 2; mi++)
                wmma::load_matrix_sync(af[mi], &sA[cur][(wm * 32 + mi * 16) * 40 + ks], 40);
            #pragma unroll
            for (int ni = 0; ni < 4; ni++) {
                wmma::fragment<wmma::matrix_b, 16, 16, 16, __half, wmma::row_major> bfr;
                wmma::load_matrix_sync(bfr, &sB[cur][ks * 136 + wn * 64 + ni * 16], 136);
                #pragma unroll
                for (int mi = 0; mi < 2; mi++)
                    wmma::mma_sync(acc[mi][ni], af[mi], bfr, acc[mi][ni]);
            }
        }
        if (it + 1 < NIT) {
            const int nxt = cur ^ 1;
            *(uint4*)&sA[nxt][am * 40 + ak]     = aR0;
            *(uint4*)&sA[nxt][am * 40 + ak + 8] = aR1;
            *(uint4*)&sB[nxt][bkr * 136 + bch]     = bR0;
            *(uint4*)&sB[nxt][bkr * 136 + bch + 8] = bR1;
            __syncthreads();
        }
    }

    float* cw = &sC[warp * 256];
    const int erow = lane >> 1, ec0 = (lane & 1) * 8;
    #pragma unroll
    for (int mi = 0; mi < 2; mi++)
        #pragma unroll
        for (int ni = 0; ni < 4; ni++) {
            wmma::store_matrix_sync(cw, acc[mi][ni], 16, wmma::mem_row_major);
            __syncwarp();
            const float* s = &cw[erow * 16 + ec0];
            __half out[8];
            #pragma unroll
            for (int q = 0; q < 8; q++) out[q] = H16(s[q]);
            *(uint4*)&C[(size_t)(mt0 + wm * 32 + mi * 16 + erow) * G3P
                        + n0 + wn * 64 + ni * 16 + ec0] = *(uint4*)out;
            __syncwarp();
        }
}

// =================== 2. persistent GRU: all 64 steps, both dirs, one launch ===================
// grid = 256 blocks x 256 threads, all co-resident (<= 148 SMs x 2). 512 tiles/step,
// 2 tiles per block. Software grid barrier between steps.
__global__ __launch_bounds__(256, 2) void gru_persistent(
    const float* __restrict__ bhhf, const float* __restrict__ bhhr)
{
    // mainloop: sH 2x5120B @0, sW 2x13824B @10240; epilogue sC (24576B) aliases @0
    __shared__ __align__(16) char smemRaw[10240 + 27648];
    __half (*sH)[64 * 40] = (__half (*)[64 * 40])smemRaw;
    __half (*sW)[3 * 32 * 72] = (__half (*)[3 * 32 * 72])(smemRaw + 10240);
    float* sCall = (float*)smemRaw;

    const int tid = threadIdx.x;
    const int warp = tid >> 5, lane = tid & 31;
    const int wm = warp >> 1, wn = warp & 1;
    const size_t gstep = (size_t)HPH * HPH;

    for (int s = 0; s < TT; s++) {
        #pragma unroll
        for (int w = 0; w < 2; w++) {
            const int tile = blockIdx.x + w * GRU_BLOCKS;   // 0..511
            const int dir = tile >> 8;
            const int rem = tile & 255;
            const int j0 = (rem & 3) * 64;
            const int b0 = (rem >> 2) * 64;

            const int t = dir ? (TT - 1 - s) : s;
            const float* bhh = dir ? bhhr : bhhf;
            const __half* xgt = g_xg + (size_t)dir * M_TOT * G3P + (size_t)t * BDIM * G3P;
            const __half* Whd = g_Whh + (size_t)dir * 3 * HPH * HPH;
            float* hbase = dir ? g_hr : g_hf;
            __half* hhbase = dir ? g_hrh : g_hfh;
            const int slab_prev = dir ? (t + 1) : t;
            const int slab_out  = dir ? t : (t + 1);
            const float*  hprev  = hbase + (size_t)slab_prev * BDIM * HP;
            float*        hout   = hbase + (size_t)slab_out * BDIM * HP;
            const __half* hprevh = hhbase + (size_t)slab_prev * BDIM * HPH;
            __half*       houth  = hhbase + (size_t)slab_out * BDIM * HPH;

            wmma::fragment<wmma::accumulator, 16, 16, 16, float> acc[3][2];
            #pragma unroll
            for (int g = 0; g < 3; g++)
                #pragma unroll
                for (int p = 0; p < 2; p++) wmma::fill_fragment(acc[g][p], 0.f);

            const int hrow = tid >> 2, hch = (tid & 3) * 8;
            const __half* hp = hprevh + (size_t)(b0 + hrow) * HPH + hch;
            const int wkr = tid >> 3, wch = (tid & 7) * 8;
            const __half* wp0 = Whd + (size_t)wkr * HPH + j0 + wch;

            uint4 hR = *(const uint4*)hp;
            uint4 wR[3];
            #pragma unroll
            for (int g = 0; g < 3; g++) wR[g] = *(const uint4*)(wp0 + g * gstep);

            __syncthreads();   // smem free of previous tile's readers
            *(uint4*)&sH[0][hrow * 40 + hch] = hR;
            #pragma unroll
            for (int g = 0; g < 3; g++) *(uint4*)&sW[0][(g * 32 + wkr) * 72 + wch] = wR[g];
            __syncthreads();

            const int NIT = HPH / 32;  // 8
            for (int it = 0; it < NIT; ++it) {
                const int cur = it & 1;
                if (it + 1 < NIT) {
                    int k0 = (it + 1) * 32;
                    hR = *(const uint4*)(hp + k0);
                    #pragma unroll
                    for (int g = 0; g < 3; g++)
                        wR[g] = *(const uint4*)(wp0 + g * gstep + (size_t)k0 * HPH);
                }
                #pragma unroll
                for (int ks = 0; ks < 32; ks += 16) {
                    wmma::fragment<wmma::matrix_a, 16, 16, 16, __half, wmma::row_major> af;
                    wmma::load_matrix_sync(af, &sH[cur][(wm * 16) * 40 + ks], 40);
                    #pragma unroll
                    for (int g = 0; g < 3; g++)
                        #pragma unroll
                        for (int p = 0; p < 2; p++) {
                            wmma::fragment<wmma::matrix_b, 16, 16, 16, __half, wmma::row_major> bfr;
                            wmma::load_matrix_sync(bfr, &sW[cur][(g * 32 + ks) * 72 + wn * 32 + p * 16], 72);
                            wmma::mma_sync(acc[g][p], af, bfr, acc[g][p]);
                        }
                }
                if (it + 1 < NIT) {
                    const int nxt = cur ^ 1;
                    *(uint4*)&sH[nxt][hrow * 40 + hch] = hR;
                    #pragma unroll
                    for (int g = 0; g < 3; g++) *(uint4*)&sW[nxt][(g * 32 + wkr) * 72 + wch] = wR[g];
                    __syncthreads();
                }
            }
            __syncthreads();   // repurpose smem as sC

            float* cw = &sCall[warp * 3 * 256];
            #pragma unroll
            for (int p = 0; p < 2; p++) {
                #pragma unroll
                for (int g = 0; g < 3; g++)
                    wmma::store_matrix_sync(cw + g * 256, acc[g][p], 16, wmma::mem_row_major);
                __syncwarp();
                {
                    int row = lane >> 1, c0 = (lane & 1) * 8;
                    int b = b0 + wm * 16 + row;
                    const __half* xr = xgt + (size_t)b * G3P;
                    const float* hpr = hprev + (size_t)b * HP;
                    float* hor = hout + (size_t)b * HP;
                    __half* horh = houth + (size_t)b * HPH;
                    #pragma unroll
                    for (int q = 0; q < 8; q++) {
                        int e = row * 16 + c0 + q;
                        int j = j0 + wn * 32 + p * 16 + c0 + q;
                        if (j < HH) {
                            float cr = cw[0 * 256 + e], cz = cw[1 * 256 + e], cn = cw[2 * 256 + e];
                            float r = 1.f / (1.f + __expf(-(__half2float(xr[j]) + cr + bhh[j])));
                            float z = 1.f / (1.f + __expf(-(__half2float(xr[HH + j]) + cz + bhh[HH + j])));
                            float nn = tanhf(__half2float(xr[2 * HH + j]) + r * (cn + bhh[2 * HH + j]));
                            float val = (1.f - z) * nn + z * hpr[j];
                            hor[j] = val;
                            horh[j] = H16(val);
                        }
                    }
                }
                __syncwarp();
            }
        }

        // ---- software grid barrier (sense via generation counter) ----
        if (s + 1 < TT) {
            __syncthreads();
            if (tid == 0) {
                __threadfence();                               // publish this step's h writes
                unsigned gen = *(volatile unsigned*)&g_barG;   // read BEFORE arriving
                if (atomicAdd(&g_barC, 1u) == GRU_BLOCKS - 1u) {
                    g_barC = 0;
                    __threadfence();                           // order reset before release
                    atomicAdd(&g_barG, 1u);
                } else {
                    while (*(volatile unsigned*)&g_barG == gen) __nanosleep(64);
                }
                __threadfence();                               // acquire
            }
            __syncthreads();
        }
    }
}

// =================== 3. word attention scores (fp16, double-buffered) ===================
__global__ __launch_bounds__(256, 2) void word_score3(
    const float* __restrict__ bw, const float* __restrict__ pw)
{
    __shared__ __half sA[2][64 * 40];
    __shared__ __half sB[2][32 * 136];
    __shared__ float  sC[8 * 256];
    __shared__ float  srow[64];

    const int t = blockIdx.x;
    const int b0 = blockIdx.y * 64;
    const int tid = threadIdx.x;
    const int warp = tid >> 5, lane = tid & 31;
    const int wm = warp >> 2, wn = warp & 3;

    const __half* hfh = g_hfh + (size_t)(t + 1) * BDIM * HPH;
    const __half* hrh = g_hrh + (size_t)t * BDIM * HPH;

    if (tid < 64) srow[tid] = 0.f;

    const int arow = tid >> 2, ach = (tid & 3) * 8;
    const __half* af_p = hfh + (size_t)(b0 + arow) * HPH + ach;
    const __half* ar_p = hrh + (size_t)(b0 + arow) * HPH + ach;
    const int bkr = tid >> 3, bch = (tid & 7) * 16;
    const int NIT = WKP / 32;  // 16

    for (int nc = 0; nc < 512; nc += 128) {
        wmma::fragment<wmma::accumulator, 16, 16, 16, float> acc[2][2];
        #pragma unroll
        for (int mi = 0; mi < 2; mi++)
            #pragma unroll
            for (int ni = 0; ni < 2; ni++) wmma::fill_fragment(acc[mi][ni], 0.f);

        uint4 aR = *(const uint4*)af_p;
        uint4 bR0 = *(const uint4*)&g_Ww[(size_t)bkr * WNP + nc + bch];
        uint4 bR1 = *(const uint4*)&g_Ww[(size_t)bkr * WNP + nc + bch + 8];

        __syncthreads();
        *(uint4*)&sA[0][arow * 40 + ach] = aR;
        *(uint4*)&sB[0][bkr * 136 + bch]     = bR0;
        *(uint4*)&sB[0][bkr * 136 + bch + 8] = bR1;
        __syncthreads();

        for (int it = 0; it < NIT; ++it) {
            const int cur = it & 1;
            if (it + 1 < NIT) {
                int k0 = (it + 1) * 32;
                aR = (k0 < HPH) ? *(const uint4*)(af_p + k0)
                                : *(const uint4*)(ar_p + (k0 - HPH));
                bR0 = *(const uint4*)&g_Ww[(size_t)(k0 + bkr) * WNP + nc + bch];
                bR1 = *(const uint4*)&g_Ww[(size_t)(k0 + bkr) * WNP + nc + bch + 8];
            }
            #pragma unroll
            for (int ks = 0; ks < 32; ks += 16) {
                wmma::fragment<wmma::matrix_a, 16, 16, 16, __half, wmma::row_major> af[2];
                #pragma unroll
                for (int mi = 0; mi < 2; mi++)
                    wmma::load_matrix_sync(af[mi], &sA[cur][(wm * 32 + mi * 16) * 40 + ks], 40);
                #pragma unroll
                for (int ni = 0; ni < 2; ni++) {
                    wmma::fragment<wmma::matrix_b, 16, 16, 16, __half, wmma::row_major> bfr;
                    wmma::load_matrix_sync(bfr, &sB[cur][ks * 136 + wn * 32 + ni * 16], 136);
                    #pragma unroll
                    for (int mi = 0; mi < 2; mi++)
                        wmma::mma_sync(acc[mi][ni], af[mi], bfr, acc[mi][ni]);
                }
            }
            if (it + 1 < NIT) {
                const int nxt = cur ^ 1;
                *(uint4*)&sA[nxt][arow * 40 + ach] = aR;
                *(uint4*)&sB[nxt][bkr * 136 + bch]     = bR0;
                *(uint4*)&sB[nxt][bkr * 136 + bch + 8] = bR1;
                __syncthreads();
            }
        }
        float* cw = &sC[warp * 256];
        #pragma unroll
        for (int mi = 0; mi < 2; mi++)
            #pragma unroll
            for (int ni = 0; ni < 2; ni++) {
                wmma::store_matrix_sync(cw, acc[mi][ni], 16, wmma::mem_row_major);
                __syncwarp();
                float part = 0.f;
                #pragma unroll
                for (int q = 0; q < 8; q++) {
                    int e = lane * 8 + q;
                    int col = e & 15;
                    int j = nc + wn * 32 + ni * 16 + col;
                    if (j < H2) part += tanhf(cw[e] + bw[j]) * pw[j];
                }
                atomicAdd(&srow[wm * 32 + mi * 16 + (lane >> 1)], part);
                __syncwarp();
            }
    }
    __syncthreads();
    if (tid < 64) g_scores[(size_t)(b0 + tid) * TT + t] = srow[tid];
}

// =================== 4. softmax over t + weighted sum (fp16 h reads) ===================
__global__ void word_attn()
{
    __shared__ float alpha[TT];
    __shared__ float red[2];
    const int b = blockIdx.x;
    const int tid = threadIdx.x;
    if (tid < TT) alpha[tid] = g_scores[(size_t)b * TT + tid];
    __syncthreads();
    if (tid == 0) {
        float m = -1e30f;
        for (int t2 = 0; t2 < TT; t2++) m = fmaxf(m, alpha[t2]);
        red[0] = m;
    }
    __syncthreads();
    if (tid < TT) alpha[tid] = __expf(alpha[tid] - red[0]);
    __syncthreads();
    if (tid == 0) {
        float ssum = 0.f;
        for (int t2 = 0; t2 < TT; t2++) ssum += alpha[t2];
        red[1] = 1.f / ssum;
    }
    __syncthreads();
    if (tid < TT) alpha[tid] *= red[1];
    __syncthreads();
    const size_t stride = (size_t)BDIM * HPH;
    for (int hcol = tid; hcol < H2; hcol += 256) {
        const __half* base = (hcol < HH)
            ? (g_hfh + stride + (size_t)b * HPH + hcol)          // slab t+1
            : (g_hrh + (size_t)b * HPH + (hcol - HH));           // slab t
        float acc = 0.f;
        #pragma unroll 4
        for (int t2 = 0; t2 < TT; t2++) acc += alpha[t2] * __half2float(base[(size_t)t2 * stride]);
        g_wordvec[(size_t)b * H2 + hcol] = acc;
    }
}

// =================== 5. zero output ===================
__global__ void zero_out(float* __restrict__ out, int n)
{
    int i = blockIdx.x * 256 + threadIdx.x;
    if (i < n) out[i] = 0.f;
}

// =================== 6. sentence attention + FC + scatter ===================
__global__ void sent_kernel(const float* __restrict__ Wsent, const float* __restrict__ bsent,
                            const float* __restrict__ psent, const float* __restrict__ fcW,
                            const float* __restrict__ fcb, const int* __restrict__ pairs,
                            float* __restrict__ out)
{
    __shared__ float wvs[MS][H2];
    __shared__ float score[MS];
    __shared__ float beta[MS];
    __shared__ float sv[H2];
    const int nb = blockIdx.x;
    const int tid = threadIdx.x;

    for (int i = tid; i < MS * H2; i += 256)
        wvs[i / H2][i % H2] = g_wordvec[(size_t)nb * MS * H2 + i];
    if (tid < MS) score[tid] = 0.f;
    __syncthreads();

    for (int j = tid; j < H2; j += 256) {
        float acc[MS];
        #pragma unroll
        for (int s = 0; s < MS; s++) acc[s] = 0.f;
        for (int k = 0; k < H2; k++) {
            float w = Wsent[(size_t)k * H2 + j];
            #pragma unroll
            for (int s = 0; s < MS; s++) acc[s] += wvs[s][k] * w;
        }
        float bb = bsent[j], pp = psent[j];
        #pragma unroll
        for (int s = 0; s < MS; s++) atomicAdd(&score[s], tanhf(acc[s] + bb) * pp);
    }
    __syncthreads();
    if (tid == 0) {
        float m = -1e30f;
        for (int s = 0; s < MS; s++) m = fmaxf(m, score[s]);
        float sum = 0.f;
        for (int s = 0; s < MS; s++) { beta[s] = __expf(score[s] - m); sum += beta[s]; }
        float inv = 1.f / sum;
        for (int s = 0; s < MS; s++) beta[s] *= inv;
    }
    __syncthreads();
    for (int hcol = tid; hcol < H2; hcol += 256) {
        float acc = 0.f;
        #pragma unroll
        for (int s = 0; s < MS; s++) acc += beta[s] * wvs[s][hcol];
        sv[hcol] = acc;
    }
    __syncthreads();
    if (tid < NOUT) {
        int o = tid;
        float acc = fcb[o];
        for (int k = 0; k < H2; k++) acc += sv[k] * fcW[(size_t)o * H2 + k];
        int p0 = pairs[nb * 3 + 0];
        int p1 = pairs[nb * 3 + 1];
        int p2 = pairs[nb * 3 + 2];
        out[(((size_t)p0 * NENT + p1) * NENT + p2) * NOUT + o] = acc;
    }
}

// =================== launcher ===================
extern "C" void kernel_launch(void* const* d_in, const int* in_sizes, int n_in,
                              void* d_out, int out_size)
{
    const float* bag       = (const float*)d_in[0];
    const float* W_ih_f    = (const float*)d_in[1];
    const float* W_hh_f    = (const float*)d_in[2];
    const float* b_ih_f    = (const float*)d_in[3];
    const float* b_hh_f    = (const float*)d_in[4];
    const float* W_ih_r    = (const float*)d_in[5];
    const float* W_hh_r    = (const float*)d_in[6];
    const float* b_ih_r    = (const float*)d_in[7];
    const float* b_hh_r    = (const float*)d_in[8];
    const float* W_word    = (const float*)d_in[9];
    const float* b_word    = (const float*)d_in[10];
    const float* proj_word = (const float*)d_in[11];
    const float* W_sent    = (const float*)d_in[12];
    const float* b_sent    = (const float*)d_in[13];
    const float* proj_sent = (const float*)d_in[14];
    const float* fc_W      = (const float*)d_in[15];
    const float* fc_b      = (const float*)d_in[16];
    const int*   pairs     = (const int*)d_in[17];
    float* out = (float*)d_out;

    // 0. pre-convert operands to fp16 MMA-ready layouts
    {
        size_t nx = (size_t)M_TOT * 46;
        conv_x<<<(unsigned)((nx + 255) / 256), 256>>>(bag);
        int nwih = 2 * 361 * G3;
        conv_wih<<<(nwih + 255) / 256, 256>>>(W_ih_f, b_ih_f, W_ih_r, b_ih_r);
        int nwhh = 2 * 3 * HH * HH;
        conv_whh<<<(nwhh + 255) / 256, 256>>>(W_hh_f, W_hh_r);
        int nww = WKP * H2;
        conv_ww<<<(nww + 255) / 256, 256>>>(W_word);
    }

    // 1. input GEMMs (bias folded via ones-column)
    dim3 gI(NXP / 128, M_TOT / 128, 2);
    input_gemm3<<<gI, 256>>>();

    // 2. all 64 GRU steps, both dirs: ONE persistent launch with grid barrier
    gru_persistent<<<GRU_BLOCKS, 256>>>(b_hh_f, b_hh_r);

    // 3. word attention scores
    dim3 gW(TT, BDIM / 64);
    word_score3<<<gW, 256>>>(b_word, proj_word);

    // 4. softmax over t + word_vec
    word_attn<<<BDIM, 256>>>();

    // 5. zero output buffer
    int n_out = NDOCS * NENT * NENT * NOUT;
    zero_out<<<(n_out + 255) / 256, 256>>>(out, n_out);

    // 6. sentence attention + FC + scatter
    sent_kernel<<<NBAG, 256>>>(W_sent, b_sent, proj_sent, fc_W, fc_b, pairs, out);
}

// round 13
// speedup vs baseline: 1.0247x; 1.0247x over previous
#include <cuda_runtime.h>
#include <cuda_fp16.h>
#include <mma.h>
#include <math.h>

using namespace nvcuda;

#define NBAG 512
#define MS 8
#define TT 64
#define BDIM 4096          // NBAG*MS
#define INDIM 360
#define HH 230
#define H2 460
#define G3 690
#define G3P 768            // xg row stride
#define NOUT 53
#define NDOCS 32
#define NENT 8
#define HP 232             // fp32 h row stride
#define HPH 256            // fp16 h row stride / Whh k,j pad
#define KXP 384            // input K pad (360 data + ones@360 + 0s)
#define NXP 768            // Wih n pad (= G3P, unguarded tiles)
#define WKP 512            // word K pad (256 + 256)
#define WNP 464            // word n pad
#define M_TOT (BDIM * TT)  // 262144

// ------------------- scratch (device globals; zero-initialized at module load) -------------------
__device__ __align__(256) __half g_xh[(size_t)M_TOT * KXP];          // bag fp16, m' = t*BDIM+b
__device__ __align__(256) __half g_Wih[2ull * KXP * NXP];            // [dir][k][n], bias at k=360
__device__ __align__(256) __half g_xg[2ull * M_TOT * G3P];           // [dir][t][b][768]
__device__ __align__(256) __half g_Whh[2ull * 3 * HPH * HPH];        // [dir][g][k][j]
__device__ __align__(256) __half g_Ww[(size_t)WKP * WNP];            // word W, k-gap baked
__device__ float g_hf[(size_t)(TT + 1) * BDIM * HP];                 // fp32 h (blend)
__device__ float g_hr[(size_t)(TT + 1) * BDIM * HP];
__device__ __align__(256) __half g_hfh[(size_t)(TT + 1) * BDIM * HPH];  // fp16 h (MMA/attn)
__device__ __align__(256) __half g_hrh[(size_t)(TT + 1) * BDIM * HPH];
__device__ float g_scores[(size_t)BDIM * TT];
__device__ float g_wordvec[(size_t)BDIM * H2];

#define H16(x) __float2half(x)

// =================== prep kernels ===================
__global__ void conv_x(const float* __restrict__ bag)
{
    size_t idx = (size_t)blockIdx.x * 256 + threadIdx.x;
    const size_t total = (size_t)M_TOT * 46;
    if (idx >= total) return;
    size_t m = idx / 46;
    int kc = (int)(idx % 46) * 8;
    int t = (int)(m >> 12), b = (int)(m & (BDIM - 1));
    __half out[8];
    if (kc < INDIM) {
        const float* src = bag + ((size_t)b * TT + t) * INDIM + kc;
        float4 v0 = *(const float4*)src;
        float4 v1 = *(const float4*)(src + 4);
        out[0] = H16(v0.x); out[1] = H16(v0.y); out[2] = H16(v0.z); out[3] = H16(v0.w);
        out[4] = H16(v1.x); out[5] = H16(v1.y); out[6] = H16(v1.z); out[7] = H16(v1.w);
    } else {   // kc == 360: ones column for bias folding, then zeros
        out[0] = H16(1.f);
        #pragma unroll
        for (int q = 1; q < 8; q++) out[q] = H16(0.f);
    }
    *(uint4*)&g_xh[m * KXP + kc] = *(uint4*)out;
}

__global__ void conv_wih(const float* __restrict__ Wf, const float* __restrict__ bf_,
                         const float* __restrict__ Wr, const float* __restrict__ br_)
{
    int idx = blockIdx.x * 256 + threadIdx.x;
    const int per = 361 * G3;
    if (idx >= 2 * per) return;
    int dir = idx / per, r = idx % per;
    int k = r / G3, n = r % G3;
    const float* W = dir ? Wr : Wf;
    const float* bias = dir ? br_ : bf_;
    float v = (k < INDIM) ? W[(size_t)n * INDIM + k] : bias[n];
    g_Wih[((size_t)dir * KXP + k) * NXP + n] = H16(v);
}

__global__ void conv_whh(const float* __restrict__ Wf, const float* __restrict__ Wr)
{
    int idx = blockIdx.x * 256 + threadIdx.x;
    const int per = 3 * HH * HH;
    if (idx >= 2 * per) return;
    int dir = idx / per, r = idx % per;
    int g = r / (HH * HH); r %= HH * HH;
    int k = r / HH, j = r % HH;
    const float* W = dir ? Wr : Wf;
    g_Whh[(((size_t)dir * 3 + g) * HPH + k) * HPH + j] = H16(W[(size_t)(g * HH + j) * HH + k]);
}

__global__ void conv_ww(const float* __restrict__ Ww)
{
    int idx = blockIdx.x * 256 + threadIdx.x;
    if (idx >= WKP * H2) return;
    int kp = idx / H2, j = idx % H2;
    int ksrc = (kp < HH) ? kp : ((kp >= HPH && kp < HPH + HH) ? (kp - (HPH - HH)) : -1);
    if (ksrc >= 0)
        g_Ww[(size_t)kp * WNP + j] = H16(Ww[(size_t)ksrc * H2 + j]);
}

// =================== 1. input GEMM: xg = xh @ Wih (bias via ones-column) ===================
// M=262144, N=768 (6 tiles of 128), K=384 (12 slabs of 32). 8 warps 4x2, warp 32x64.
// 2-stage smem double buffering; launch_bounds(256,2) caps regs at 128 -> 2 blocks/SM.
__global__ __launch_bounds__(256, 2) void input_gemm3()
{
    __shared__ __half sA[2][128 * 40];
    __shared__ __half sB[2][32 * 136];
    __shared__ float  sC[8 * 256];

    const int dir = blockIdx.z;
    const __half* Wh = g_Wih + (size_t)dir * KXP * NXP;
    __half* C = g_xg + (size_t)dir * M_TOT * G3P;

    const int n0 = blockIdx.x * 128;
    const int mt0 = blockIdx.y * 128;
    const int tid = threadIdx.x;
    const int warp = tid >> 5, lane = tid & 31;
    const int wm = warp >> 1, wn = warp & 1;

    wmma::fragment<wmma::accumulator, 16, 16, 16, float> acc[2][4];
    #pragma unroll
    for (int i = 0; i < 2; i++)
        #pragma unroll
        for (int j = 0; j < 4; j++) wmma::fill_fragment(acc[i][j], 0.f);

    const int am = tid >> 1, ak = (tid & 1) * 16;
    const __half* ap = g_xh + (size_t)(mt0 + am) * KXP + ak;
    const int bkr = tid >> 3, bch = (tid & 7) * 16;
    const __half* bp = Wh + (size_t)bkr * NXP + n0 + bch;

    uint4 aR0 = *(const uint4*)ap;
    uint4 aR1 = *(const uint4*)(ap + 8);
    uint4 bR0 = *(const uint4*)bp;
    uint4 bR1 = *(const uint4*)(bp + 8);

    const int NIT = KXP / 32;  // 12
    *(uint4*)&sA[0][am * 40 + ak]     = aR0;
    *(uint4*)&sA[0][am * 40 + ak + 8] = aR1;
    *(uint4*)&sB[0][bkr * 136 + bch]     = bR0;
    *(uint4*)&sB[0][bkr * 136 + bch + 8] = bR1;
    __syncthreads();

    for (int it = 0; it < NIT; ++it) {
        const int cur = it & 1;
        if (it + 1 < NIT) {
            int k0 = (it + 1) * 32;
            aR0 = *(const uint4*)(ap + k0);
            aR1 = *(const uint4*)(ap + k0 + 8);
            bR0 = *(const uint4*)(bp + (size_t)k0 * NXP);
            bR1 = *(const uint4*)(bp + (size_t)k0 * NXP + 8);
        }
        #pragma unroll
        for (int ks = 0; ks < 32; ks += 16) {
            wmma::fragment<wmma::matrix_a, 16, 16, 16, __half, wmma::row_major> af[2];
            #pragma unroll
            for (int mi = 0; mi < 2; mi++)
                wmma::load_matrix_sync(af[mi], &sA[cur][(wm * 32 + mi * 16) * 40 + ks], 40);
            #pragma unroll
            for (int ni = 0; ni < 4; ni++) {
                wmma::fragment<wmma::matrix_b, 16, 16, 16, __half, wmma::row_major> bfr;
                wmma::load_matrix_sync(bfr, &sB[cur][ks * 136 + wn * 64 + ni * 16], 136);
                #pragma unroll
                for (int mi = 0; mi < 2; mi++)
                    wmma::mma_sync(acc[mi][ni], af[mi], bfr, acc[mi][ni]);
            }
        }
        if (it + 1 < NIT) {
            const int nxt = cur ^ 1;
            *(uint4*)&sA[nxt][am * 40 + ak]     = aR0;
            *(uint4*)&sA[nxt][am * 40 + ak + 8] = aR1;
            *(uint4*)&sB[nxt][bkr * 136 + bch]     = bR0;
            *(uint4*)&sB[nxt][bkr * 136 + bch + 8] = bR1;
            __syncthreads();
        }
    }

    float* cw = &sC[warp * 256];
    const int erow = lane >> 1, ec0 = (lane & 1) * 8;
    #pragma unroll
    for (int mi = 0; mi < 2; mi++)
        #pragma unroll
        for (int ni = 0; ni < 4; ni++) {
            wmma::store_matrix_sync(cw, acc[mi][ni], 16, wmma::mem_row_major);
            __syncwarp();
            const float* s = &cw[erow * 16 + ec0];
            __half out[8];
            #pragma unroll
            for (int q = 0; q < 8; q++) out[q] = H16(s[q]);
            *(uint4*)&C[(size_t)(mt0 + wm * 32 + mi * 16 + erow) * G3P
                        + n0 + wn * 64 + ni * 16 + ec0] = *(uint4*)out;
            __syncwarp();
        }
}

// =================== 2. GRU step (fp16, double-buffered, sC aliased) ===================
// per block: 64 b x 64 j, 3 gates. K: 8 slabs of 32. 8 warps 4x2 (warp 16x32 per gate).
__global__ __launch_bounds__(256, 2) void gru_step3(
    const float* __restrict__ bhhf, const float* __restrict__ bhhr, int s)
{
    // mainloop buffers: sH 2x5120B @0, sW 2x13824B @10240; epilogue sC (24576B) aliases @0
    __shared__ __align__(16) char smemRaw[10240 + 27648];
    __half (*sH)[64 * 40] = (__half (*)[64 * 40])smemRaw;
    __half (*sW)[3 * 32 * 72] = (__half (*)[3 * 32 * 72])(smemRaw + 10240);
    float* sCall = (float*)smemRaw;

    const int dir = blockIdx.z;
    const int t = dir ? (TT - 1 - s) : s;
    const float* bhh = dir ? bhhr : bhhf;
    const __half* xgt = g_xg + (size_t)dir * M_TOT * G3P + (size_t)t * BDIM * G3P;
    const __half* Whd = g_Whh + (size_t)dir * 3 * HPH * HPH;
    float* hbase = dir ? g_hr : g_hf;
    __half* hhbase = dir ? g_hrh : g_hfh;
    const int slab_prev = dir ? (t + 1) : t;
    const int slab_out  = dir ? t : (t + 1);
    const float*  hprev  = hbase + (size_t)slab_prev * BDIM * HP;
    float*        hout   = hbase + (size_t)slab_out * BDIM * HP;
    const __half* hprevh = hhbase + (size_t)slab_prev * BDIM * HPH;
    __half*       houth  = hhbase + (size_t)slab_out * BDIM * HPH;

    const int j0 = blockIdx.x * 64;
    const int b0 = blockIdx.y * 64;
    const int tid = threadIdx.x;
    const int warp = tid >> 5, lane = tid & 31;
    const int wm = warp >> 1, wn = warp & 1;

    wmma::fragment<wmma::accumulator, 16, 16, 16, float> acc[3][2];
    #pragma unroll
    for (int g = 0; g < 3; g++)
        #pragma unroll
        for (int p = 0; p < 2; p++) wmma::fill_fragment(acc[g][p], 0.f);

    const int hrow = tid >> 2, hch = (tid & 3) * 8;
    const __half* hp = hprevh + (size_t)(b0 + hrow) * HPH + hch;
    const int wkr = tid >> 3, wch = (tid & 7) * 8;
    const __half* wp0 = Whd + (size_t)wkr * HPH + j0 + wch;
    const size_t gstep = (size_t)HPH * HPH;

    uint4 hR = *(const uint4*)hp;
    uint4 wR[3];
    #pragma unroll
    for (int g = 0; g < 3; g++) wR[g] = *(const uint4*)(wp0 + g * gstep);

    const int NIT = HPH / 32;  // 8
    *(uint4*)&sH[0][hrow * 40 + hch] = hR;
    #pragma unroll
    for (int g = 0; g < 3; g++) *(uint4*)&sW[0][(g * 32 + wkr) * 72 + wch] = wR[g];
    __syncthreads();

    for (int it = 0; it < NIT; ++it) {
        const int cur = it & 1;
        if (it + 1 < NIT) {
            int k0 = (it + 1) * 32;
            hR = *(const uint4*)(hp + k0);
            #pragma unroll
            for (int g = 0; g < 3; g++)
                wR[g] = *(const uint4*)(wp0 + g * gstep + (size_t)k0 * HPH);
        }
        #pragma unroll
        for (int ks = 0; ks < 32; ks += 16) {
            wmma::fragment<wmma::matrix_a, 16, 16, 16, __half, wmma::row_major> af;
            wmma::load_matrix_sync(af, &sH[cur][(wm * 16) * 40 + ks], 40);
            #pragma unroll
            for (int g = 0; g < 3; g++)
                #pragma unroll
                for (int p = 0; p < 2; p++) {
                    wmma::fragment<wmma::matrix_b, 16, 16, 16, __half, wmma::row_major> bfr;
                    wmma::load_matrix_sync(bfr, &sW[cur][(g * 32 + ks) * 72 + wn * 32 + p * 16], 72);
                    wmma::mma_sync(acc[g][p], af, bfr, acc[g][p]);
                }
        }
        if (it + 1 < NIT) {
            const int nxt = cur ^ 1;
            *(uint4*)&sH[nxt][hrow * 40 + hch] = hR;
            #pragma unroll
            for (int g = 0; g < 3; g++) *(uint4*)&sW[nxt][(g * 32 + wkr) * 72 + wch] = wR[g];
            __syncthreads();
        }
    }
    __syncthreads();   // repurpose smem as sC

    float* cw = &sCall[warp * 3 * 256];
    #pragma unroll
    for (int p = 0; p < 2; p++) {
        #pragma unroll
        for (int g = 0; g < 3; g++)
            wmma::store_matrix_sync(cw + g * 256, acc[g][p], 16, wmma::mem_row_major);
        __syncwarp();
        {
            int row = lane >> 1, c0 = (lane & 1) * 8;
            int b = b0 + wm * 16 + row;
            const __half* xr = xgt + (size_t)b * G3P;
            const float* hpr = hprev + (size_t)b * HP;
            float* hor = hout + (size_t)b * HP;
            __half* horh = houth + (size_t)b * HPH;
            #pragma unroll
            for (int q = 0; q < 8; q++) {
                int e = row * 16 + c0 + q;
                int j = j0 + wn * 32 + p * 16 + c0 + q;
                if (j < HH) {
                    float cr = cw[0 * 256 + e], cz = cw[1 * 256 + e], cn = cw[2 * 256 + e];
                    float r = 1.f / (1.f + __expf(-(__half2float(xr[j]) + cr + bhh[j])));
                    float z = 1.f / (1.f + __expf(-(__half2float(xr[HH + j]) + cz + bhh[HH + j])));
                    float nn = tanhf(__half2float(xr[2 * HH + j]) + r * (cn + bhh[2 * HH + j]));
                    float val = (1.f - z) * nn + z * hpr[j];
                    hor[j] = val;
                    horh[j] = H16(val);
                }
            }
        }
        __syncwarp();
    }
}

// =================== 3. word attention scores (fp16, double-buffered) ===================
__global__ __launch_bounds__(256, 2) void word_score3(
    const float* __restrict__ bw, const float* __restrict__ pw)
{
    __shared__ __half sA[2][64 * 40];
    __shared__ __half sB[2][32 * 136];
    __shared__ float  sC[8 * 256];
    __shared__ float  srow[64];

    const int t = blockIdx.x;
    const int b0 = blockIdx.y * 64;
    const int tid = threadIdx.x;
    const int warp = tid >> 5, lane = tid & 31;
    const int wm = warp >> 2, wn = warp & 3;

    const __half* hfh = g_hfh + (size_t)(t + 1) * BDIM * HPH;
    const __half* hrh = g_hrh + (size_t)t * BDIM * HPH;

    if (tid < 64) srow[tid] = 0.f;

    const int arow = tid >> 2, ach = (tid & 3) * 8;
    const __half* af_p = hfh + (size_t)(b0 + arow) * HPH + ach;
    const __half* ar_p = hrh + (size_t)(b0 + arow) * HPH + ach;
    const int bkr = tid >> 3, bch = (tid & 7) * 16;
    const int NIT = WKP / 32;  // 16

    for (int nc = 0; nc < 512; nc += 128) {
        wmma::fragment<wmma::accumulator, 16, 16, 16, float> acc[2][2];
        #pragma unroll
        for (int mi = 0; mi < 2; mi++)
            #pragma unroll
            for (int ni = 0; ni < 2; ni++) wmma::fill_fragment(acc[mi][ni], 0.f);

        uint4 aR = *(const uint4*)af_p;
        uint4 bR0 = *(const uint4*)&g_Ww[(size_t)bkr * WNP + nc + bch];
        uint4 bR1 = *(const uint4*)&g_Ww[(size_t)bkr * WNP + nc + bch + 8];

        __syncthreads();
        *(uint4*)&sA[0][arow * 40 + ach] = aR;
        *(uint4*)&sB[0][bkr * 136 + bch]     = bR0;
        *(uint4*)&sB[0][bkr * 136 + bch + 8] = bR1;
        __syncthreads();

        for (int it = 0; it < NIT; ++it) {
            const int cur = it & 1;
            if (it + 1 < NIT) {
                int k0 = (it + 1) * 32;
                aR = (k0 < HPH) ? *(const uint4*)(af_p + k0)
                                : *(const uint4*)(ar_p + (k0 - HPH));
                bR0 = *(const uint4*)&g_Ww[(size_t)(k0 + bkr) * WNP + nc + bch];
                bR1 = *(const uint4*)&g_Ww[(size_t)(k0 + bkr) * WNP + nc + bch + 8];
            }
            #pragma unroll
            for (int ks = 0; ks < 32; ks += 16) {
                wmma::fragment<wmma::matrix_a, 16, 16, 16, __half, wmma::row_major> af[2];
                #pragma unroll
                for (int mi = 0; mi < 2; mi++)
                    wmma::load_matrix_sync(af[mi], &sA[cur][(wm * 32 + mi * 16) * 40 + ks], 40);
                #pragma unroll
                for (int ni = 0; ni < 2; ni++) {
                    wmma::fragment<wmma::matrix_b, 16, 16, 16, __half, wmma::row_major> bfr;
                    wmma::load_matrix_sync(bfr, &sB[cur][ks * 136 + wn * 32 + ni * 16], 136);
                    #pragma unroll
                    for (int mi = 0; mi < 2; mi++)
                        wmma::mma_sync(acc[mi][ni], af[mi], bfr, acc[mi][ni]);
                }
            }
            if (it + 1 < NIT) {
                const int nxt = cur ^ 1;
                *(uint4*)&sA[nxt][arow * 40 + ach] = aR;
                *(uint4*)&sB[nxt][bkr * 136 + bch]     = bR0;
                *(uint4*)&sB[nxt][bkr * 136 + bch + 8] = bR1;
                __syncthreads();
            }
        }
        float* cw = &sC[warp * 256];
        #pragma unroll
        for (int mi = 0; mi < 2; mi++)
            #pragma unroll
            for (int ni = 0; ni < 2; ni++) {
                wmma::store_matrix_sync(cw, acc[mi][ni], 16, wmma::mem_row_major);
                __syncwarp();
                float part = 0.f;
                #pragma unroll
                for (int q = 0; q < 8; q++) {
                    int e = lane * 8 + q;
                    int col = e & 15;
                    int j = nc + wn * 32 + ni * 16 + col;
                    if (j < H2) part += tanhf(cw[e] + bw[j]) * pw[j];
                }
                atomicAdd(&srow[wm * 32 + mi * 16 + (lane >> 1)], part);
                __syncwarp();
            }
    }
    __syncthreads();
    if (tid < 64) g_scores[(size_t)(b0 + tid) * TT + t] = srow[tid];
}

// =================== 4. softmax over t + weighted sum (fp16 h reads) ===================
__global__ void word_attn()
{
    __shared__ float alpha[TT];
    __shared__ float red[2];
    const int b = blockIdx.x;
    const int tid = threadIdx.x;
    if (tid < TT) alpha[tid] = g_scores[(size_t)b * TT + tid];
    __syncthreads();
    if (tid == 0) {
        float m = -1e30f;
        for (int t2 = 0; t2 < TT; t2++) m = fmaxf(m, alpha[t2]);
        red[0] = m;
    }
    __syncthreads();
    if (tid < TT) alpha[tid] = __expf(alpha[tid] - red[0]);
    __syncthreads();
    if (tid == 0) {
        float ssum = 0.f;
        for (int t2 = 0; t2 < TT; t2++) ssum += alpha[t2];
        red[1] = 1.f / ssum;
    }
    __syncthreads();
    if (tid < TT) alpha[tid] *= red[1];
    __syncthreads();
    const size_t stride = (size_t)BDIM * HPH;
    for (int hcol = tid; hcol < H2; hcol += 256) {
        const __half* base = (hcol < HH)
            ? (g_hfh + stride + (size_t)b * HPH + hcol)          // slab t+1
            : (g_hrh + (size_t)b * HPH + (hcol - HH));           // slab t
        float acc = 0.f;
        #pragma unroll 4
        for (int t2 = 0; t2 < TT; t2++) acc += alpha[t2] * __half2float(base[(size_t)t2 * stride]);
        g_wordvec[(size_t)b * H2 + hcol] = acc;
    }
}

// =================== 5. zero output ===================
__global__ void zero_out(float* __restrict__ out, int n)
{
    int i = blockIdx.x * 256 + threadIdx.x;
    if (i < n) out[i] = 0.f;
}

// =================== 6. sentence attention + FC + scatter ===================
__global__ void sent_kernel(const float* __restrict__ Wsent, const float* __restrict__ bsent,
                            const float* __restrict__ psent, const float* __restrict__ fcW,
                            const float* __restrict__ fcb, const int* __restrict__ pairs,
                            float* __restrict__ out)
{
    __shared__ float wvs[MS][H2];
    __shared__ float score[MS];
    __shared__ float beta[MS];
    __shared__ float sv[H2];
    const int nb = blockIdx.x;
    const int tid = threadIdx.x;

    for (int i = tid; i < MS * H2; i += 256)
        wvs[i / H2][i % H2] = g_wordvec[(size_t)nb * MS * H2 + i];
    if (tid < MS) score[tid] = 0.f;
    __syncthreads();

    for (int j = tid; j < H2; j += 256) {
        float acc[MS];
        #pragma unroll
        for (int s = 0; s < MS; s++) acc[s] = 0.f;
        for (int k = 0; k < H2; k++) {
            float w = Wsent[(size_t)k * H2 + j];
            #pragma unroll
            for (int s = 0; s < MS; s++) acc[s] += wvs[s][k] * w;
        }
        float bb = bsent[j], pp = psent[j];
        #pragma unroll
        for (int s = 0; s < MS; s++) atomicAdd(&score[s], tanhf(acc[s] + bb) * pp);
    }
    __syncthreads();
    if (tid == 0) {
        float m = -1e30f;
        for (int s = 0; s < MS; s++) m = fmaxf(m, score[s]);
        float sum = 0.f;
        for (int s = 0; s < MS; s++) { beta[s] = __expf(score[s] - m); sum += beta[s]; }
        float inv = 1.f / sum;
        for (int s = 0; s < MS; s++) beta[s] *= inv;
    }
    __syncthreads();
    for (int hcol = tid; hcol < H2; hcol += 256) {
        float acc = 0.f;
        #pragma unroll
        for (int s = 0; s < MS; s++) acc += beta[s] * wvs[s][hcol];
        sv[hcol] = acc;
    }
    __syncthreads();
    if (tid < NOUT) {
        int o = tid;
        float acc = fcb[o];
        for (int k = 0; k < H2; k++) acc += sv[k] * fcW[(size_t)o * H2 + k];
        int p0 = pairs[nb * 3 + 0];
        int p1 = pairs[nb * 3 + 1];
        int p2 = pairs[nb * 3 + 2];
        out[(((size_t)p0 * NENT + p1) * NENT + p2) * NOUT + o] = acc;
    }
}

// =================== launcher ===================
extern "C" void kernel_launch(void* const* d_in, const int* in_sizes, int n_in,
                              void* d_out, int out_size)
{
    const float* bag       = (const float*)d_in[0];
    const float* W_ih_f    = (const float*)d_in[1];
    const float* W_hh_f    = (const float*)d_in[2];
    const float* b_ih_f    = (const float*)d_in[3];
    const float* b_hh_f    = (const float*)d_in[4];
    const float* W_ih_r    = (const float*)d_in[5];
    const float* W_hh_r    = (const float*)d_in[6];
    const float* b_ih_r    = (const float*)d_in[7];
    const float* b_hh_r    = (const float*)d_in[8];
    const float* W_word    = (const float*)d_in[9];
    const float* b_word    = (const float*)d_in[10];
    const float* proj_word = (const float*)d_in[11];
    const float* W_sent    = (const float*)d_in[12];
    const float* b_sent    = (const float*)d_in[13];
    const float* proj_sent = (const float*)d_in[14];
    const float* fc_W      = (const float*)d_in[15];
    const float* fc_b      = (const float*)d_in[16];
    const int*   pairs     = (const int*)d_in[17];
    float* out = (float*)d_out;

    // 0. pre-convert operands to fp16 MMA-ready layouts
    {
        size_t nx = (size_t)M_TOT * 46;
        conv_x<<<(unsigned)((nx + 255) / 256), 256>>>(bag);
        int nwih = 2 * 361 * G3;
        conv_wih<<<(nwih + 255) / 256, 256>>>(W_ih_f, b_ih_f, W_ih_r, b_ih_r);
        int nwhh = 2 * 3 * HH * HH;
        conv_whh<<<(nwhh + 255) / 256, 256>>>(W_hh_f, W_hh_r);
        int nww = WKP * H2;
        conv_ww<<<(nww + 255) / 256, 256>>>(W_word);
    }

    // 1. input GEMMs (bias folded via ones-column), 2 blocks/SM
    dim3 gI(NXP / 128, M_TOT / 128, 2);
    input_gemm3<<<gI, 256>>>();

    // 2. 64 sequential GRU steps (fwd + rev concurrent per launch)
    dim3 gS(4, BDIM / 64, 2);
    for (int s = 0; s < TT; s++)
        gru_step3<<<gS, 256>>>(b_hh_f, b_hh_r, s);

    // 3. word attention scores
    dim3 gW(TT, BDIM / 64);
    word_score3<<<gW, 256>>>(b_word, proj_word);

    // 4. softmax over t + word_vec
    word_attn<<<BDIM, 256>>>();

    // 5. zero output buffer
    int n_out = NDOCS * NENT * NENT * NOUT;
    zero_out<<<(n_out + 255) / 256, 256>>>(out, n_out);

    // 6. sentence attention + FC + scatter
    sent_kernel<<<NBAG, 256>>>(W_sent, b_sent, proj_sent, fc_W, fc_b, pairs, out);
}

// round 14
// speedup vs baseline: 1.2095x; 1.1804x over previous
#include <cuda_runtime.h>
#include <cuda_fp16.h>
#include <mma.h>
#include <math.h>

using namespace nvcuda;

#define NBAG 512
#define MS 8
#define TT 64
#define BDIM 4096          // NBAG*MS
#define INDIM 360
#define HH 230
#define H2 460
#define G3 690
#define G3P 768            // xg row stride (3 gates x 256)
#define NOUT 53
#define NDOCS 32
#define NENT 8
#define HP 232             // fp32 h row stride
#define HPH 256            // fp16 h row stride / Whh k,j pad / xg gate stride
#define KXP 384            // input K pad (360 data + ones@360 + 0s)
#define NXP 768            // Wih n pad (= G3P, unguarded tiles)
#define WKP 512            // word K pad (256 + 256)
#define WNP 464            // word n pad
#define M_TOT (BDIM * TT)  // 262144

// ------------------- scratch (device globals; zero-initialized at module load) -------------------
__device__ __align__(256) __half g_xh[(size_t)M_TOT * KXP];          // bag fp16, m' = t*BDIM+b
__device__ __align__(256) __half g_Wih[2ull * KXP * NXP];            // [dir][k][gate*256+j], bias at k=360
__device__ __align__(256) __half g_xg[2ull * M_TOT * G3P];           // [dir][t][b][gate*256+j]
__device__ __align__(256) __half g_Whh[2ull * 3 * HPH * HPH];        // [dir][g][k][j]
__device__ __align__(256) __half g_Ww[(size_t)WKP * WNP];            // word W, k-gap baked
__device__ float g_hf[(size_t)(TT + 1) * BDIM * HP];                 // fp32 h (blend)
__device__ float g_hr[(size_t)(TT + 1) * BDIM * HP];
__device__ __align__(256) __half g_hfh[(size_t)(TT + 1) * BDIM * HPH];  // fp16 h (MMA/attn)
__device__ __align__(256) __half g_hrh[(size_t)(TT + 1) * BDIM * HPH];
__device__ float g_scores[(size_t)BDIM * TT];
__device__ float g_wordvec[(size_t)BDIM * H2];

#define H16(x) __float2half(x)

// =================== prep kernels ===================
__global__ void conv_x(const float* __restrict__ bag)
{
    size_t idx = (size_t)blockIdx.x * 256 + threadIdx.x;
    const size_t total = (size_t)M_TOT * 46;
    if (idx >= total) return;
    size_t m = idx / 46;
    int kc = (int)(idx % 46) * 8;
    int t = (int)(m >> 12), b = (int)(m & (BDIM - 1));
    __half out[8];
    if (kc < INDIM) {
        const float* src = bag + ((size_t)b * TT + t) * INDIM + kc;
        float4 v0 = *(const float4*)src;
        float4 v1 = *(const float4*)(src + 4);
        out[0] = H16(v0.x); out[1] = H16(v0.y); out[2] = H16(v0.z); out[3] = H16(v0.w);
        out[4] = H16(v1.x); out[5] = H16(v1.y); out[6] = H16(v1.z); out[7] = H16(v1.w);
    } else {   // kc == 360: ones column for bias folding, then zeros
        out[0] = H16(1.f);
        #pragma unroll
        for (int q = 1; q < 8; q++) out[q] = H16(0.f);
    }
    *(uint4*)&g_xh[m * KXP + kc] = *(uint4*)out;
}

// W_ih columns remapped to gate-padded layout: n = g*HH + j -> col g*256 + j.
// Pad cols (g*256 + [230,256)) are never written -> stay zero -> xg pads are zero.
__global__ void conv_wih(const float* __restrict__ Wf, const float* __restrict__ bf_,
                         const float* __restrict__ Wr, const float* __restrict__ br_)
{
    int idx = blockIdx.x * 256 + threadIdx.x;
    const int per = 361 * G3;
    if (idx >= 2 * per) return;
    int dir = idx / per, r = idx % per;
    int k = r / G3, n = r % G3;
    int g = n / HH, j = n % HH;
    const float* W = dir ? Wr : Wf;
    const float* bias = dir ? br_ : bf_;
    float v = (k < INDIM) ? W[(size_t)n * INDIM + k] : bias[n];
    g_Wih[((size_t)dir * KXP + k) * NXP + g * HPH + j] = H16(v);
}

__global__ void conv_whh(const float* __restrict__ Wf, const float* __restrict__ Wr)
{
    int idx = blockIdx.x * 256 + threadIdx.x;
    const int per = 3 * HH * HH;
    if (idx >= 2 * per) return;
    int dir = idx / per, r = idx % per;
    int g = r / (HH * HH); r %= HH * HH;
    int k = r / HH, j = r % HH;
    const float* W = dir ? Wr : Wf;
    g_Whh[(((size_t)dir * 3 + g) * HPH + k) * HPH + j] = H16(W[(size_t)(g * HH + j) * HH + k]);
}

__global__ void conv_ww(const float* __restrict__ Ww)
{
    int idx = blockIdx.x * 256 + threadIdx.x;
    if (idx >= WKP * H2) return;
    int kp = idx / H2, j = idx % H2;
    int ksrc = (kp < HH) ? kp : ((kp >= HPH && kp < HPH + HH) ? (kp - (HPH - HH)) : -1);
    if (ksrc >= 0)
        g_Ww[(size_t)kp * WNP + j] = H16(Ww[(size_t)ksrc * H2 + j]);
}

// =================== 1. input GEMM: xg = xh @ Wih (bias via ones-column) ===================
// M=262144, N=768 (6 tiles of 128), K=384 (12 slabs of 32). 8 warps 4x2, warp 32x64.
__global__ __launch_bounds__(256, 2) void input_gemm3()
{
    __shared__ __half sA[2][128 * 40];
    __shared__ __half sB[2][32 * 136];
    __shared__ float  sC[8 * 256];

    const int dir = blockIdx.z;
    const __half* Wh = g_Wih + (size_t)dir * KXP * NXP;
    __half* C = g_xg + (size_t)dir * M_TOT * G3P;

    const int n0 = blockIdx.x * 128;
    const int mt0 = blockIdx.y * 128;
    const int tid = threadIdx.x;
    const int warp = tid >> 5, lane = tid & 31;
    const int wm = warp >> 1, wn = warp & 1;

    wmma::fragment<wmma::accumulator, 16, 16, 16, float> acc[2][4];
    #pragma unroll
    for (int i = 0; i < 2; i++)
        #pragma unroll
        for (int j = 0; j < 4; j++) wmma::fill_fragment(acc[i][j], 0.f);

    const int am = tid >> 1, ak = (tid & 1) * 16;
    const __half* ap = g_xh + (size_t)(mt0 + am) * KXP + ak;
    const int bkr = tid >> 3, bch = (tid & 7) * 16;
    const __half* bp = Wh + (size_t)bkr * NXP + n0 + bch;

    uint4 aR0 = *(const uint4*)ap;
    uint4 aR1 = *(const uint4*)(ap + 8);
    uint4 bR0 = *(const uint4*)bp;
    uint4 bR1 = *(const uint4*)(bp + 8);

    const int NIT = KXP / 32;  // 12
    *(uint4*)&sA[0][am * 40 + ak]     = aR0;
    *(uint4*)&sA[0][am * 40 + ak + 8] = aR1;
    *(uint4*)&sB[0][bkr * 136 + bch]     = bR0;
    *(uint4*)&sB[0][bkr * 136 + bch + 8] = bR1;
    __syncthreads();

    for (int it = 0; it < NIT; ++it) {
        const int cur = it & 1;
        if (it + 1 < NIT) {
            int k0 = (it + 1) * 32;
            aR0 = *(const uint4*)(ap + k0);
            aR1 = *(const uint4*)(ap + k0 + 8);
            bR0 = *(const uint4*)(bp + (size_t)k0 * NXP);
            bR1 = *(const uint4*)(bp + (size_t)k0 * NXP + 8);
        }
        #pragma unroll
        for (int ks = 0; ks < 32; ks += 16) {
            wmma::fragment<wmma::matrix_a, 16, 16, 16, __half, wmma::row_major> af[2];
            #pragma unroll
            for (int mi = 0; mi < 2; mi++)
                wmma::load_matrix_sync(af[mi], &sA[cur][(wm * 32 + mi * 16) * 40 + ks], 40);
            #pragma unroll
            for (int ni = 0; ni < 4; ni++) {
                wmma::fragment<wmma::matrix_b, 16, 16, 16, __half, wmma::row_major> bfr;
                wmma::load_matrix_sync(bfr, &sB[cur][ks * 136 + wn * 64 + ni * 16], 136);
                #pragma unroll
                for (int mi = 0; mi < 2; mi++)
                    wmma::mma_sync(acc[mi][ni], af[mi], bfr, acc[mi][ni]);
            }
        }
        if (it + 1 < NIT) {
            const int nxt = cur ^ 1;
            *(uint4*)&sA[nxt][am * 40 + ak]     = aR0;
            *(uint4*)&sA[nxt][am * 40 + ak + 8] = aR1;
            *(uint4*)&sB[nxt][bkr * 136 + bch]     = bR0;
            *(uint4*)&sB[nxt][bkr * 136 + bch + 8] = bR1;
            __syncthreads();
        }
    }

    float* cw = &sC[warp * 256];
    const int erow = lane >> 1, ec0 = (lane & 1) * 8;
    #pragma unroll
    for (int mi = 0; mi < 2; mi++)
        #pragma unroll
        for (int ni = 0; ni < 4; ni++) {
            wmma::store_matrix_sync(cw, acc[mi][ni], 16, wmma::mem_row_major);
            __syncwarp();
            const float* s = &cw[erow * 16 + ec0];
            __half out[8];
            #pragma unroll
            for (int q = 0; q < 8; q++) out[q] = H16(s[q]);
            *(uint4*)&C[(size_t)(mt0 + wm * 32 + mi * 16 + erow) * G3P
                        + n0 + wn * 64 + ni * 16 + ec0] = *(uint4*)out;
            __syncwarp();
        }
}

// =================== 2. GRU step (fp16, double-buffered, xg register prefetch) ===================
// per block: 64 b x 64 j, 3 gates. K: 8 slabs of 32. 8 warps 4x2 (warp 16x32 per gate).
__global__ __launch_bounds__(256, 2) void gru_step3(
    const float* __restrict__ bhhf, const float* __restrict__ bhhr, int s)
{
    // mainloop buffers: sH 2x5120B @0, sW 2x13824B @10240; epilogue sC (24576B) aliases @0
    __shared__ __align__(16) char smemRaw[10240 + 27648];
    __half (*sH)[64 * 40] = (__half (*)[64 * 40])smemRaw;
    __half (*sW)[3 * 32 * 72] = (__half (*)[3 * 32 * 72])(smemRaw + 10240);
    float* sCall = (float*)smemRaw;

    const int dir = blockIdx.z;
    const int t = dir ? (TT - 1 - s) : s;
    const float* bhh = dir ? bhhr : bhhf;
    const __half* xgt = g_xg + (size_t)dir * M_TOT * G3P + (size_t)t * BDIM * G3P;
    const __half* Whd = g_Whh + (size_t)dir * 3 * HPH * HPH;
    float* hbase = dir ? g_hr : g_hf;
    __half* hhbase = dir ? g_hrh : g_hfh;
    const int slab_prev = dir ? (t + 1) : t;
    const int slab_out  = dir ? t : (t + 1);
    const float*  hprev  = hbase + (size_t)slab_prev * BDIM * HP;
    float*        hout   = hbase + (size_t)slab_out * BDIM * HP;
    const __half* hprevh = hhbase + (size_t)slab_prev * BDIM * HPH;
    __half*       houth  = hhbase + (size_t)slab_out * BDIM * HPH;

    const int j0 = blockIdx.x * 64;
    const int b0 = blockIdx.y * 64;
    const int tid = threadIdx.x;
    const int warp = tid >> 5, lane = tid & 31;
    const int wm = warp >> 1, wn = warp & 1;

    wmma::fragment<wmma::accumulator, 16, 16, 16, float> acc[3][2];
    #pragma unroll
    for (int g = 0; g < 3; g++)
        #pragma unroll
        for (int p = 0; p < 2; p++) wmma::fill_fragment(acc[g][p], 0.f);

    // ---- prefetch this thread's epilogue xg operands (gate-padded layout, uint4-aligned);
    //      xg is fully materialized before the GRU phase, so these can issue immediately
    //      and their latency overlaps the entire MMA mainloop.
    const int erow = lane >> 1, ec0 = (lane & 1) * 8;
    const int eb = b0 + wm * 16 + erow;
    const __half* xr = xgt + (size_t)eb * G3P;
    uint4 xPre[2][3];
    #pragma unroll
    for (int p = 0; p < 2; p++) {
        int j = j0 + wn * 32 + p * 16 + ec0;
        #pragma unroll
        for (int g = 0; g < 3; g++)
            xPre[p][g] = *(const uint4*)(xr + g * HPH + j);
    }

    const int hrow = tid >> 2, hch = (tid & 3) * 8;
    const __half* hp = hprevh + (size_t)(b0 + hrow) * HPH + hch;
    const int wkr = tid >> 3, wch = (tid & 7) * 8;
    const __half* wp0 = Whd + (size_t)wkr * HPH + j0 + wch;
    const size_t gstep = (size_t)HPH * HPH;

    uint4 hR = *(const uint4*)hp;
    uint4 wR[3];
    #pragma unroll
    for (int g = 0; g < 3; g++) wR[g] = *(const uint4*)(wp0 + g * gstep);

    const int NIT = HPH / 32;  // 8
    *(uint4*)&sH[0][hrow * 40 + hch] = hR;
    #pragma unroll
    for (int g = 0; g < 3; g++) *(uint4*)&sW[0][(g * 32 + wkr) * 72 + wch] = wR[g];
    __syncthreads();

    for (int it = 0; it < NIT; ++it) {
        const int cur = it & 1;
        if (it + 1 < NIT) {
            int k0 = (it + 1) * 32;
            hR = *(const uint4*)(hp + k0);
            #pragma unroll
            for (int g = 0; g < 3; g++)
                wR[g] = *(const uint4*)(wp0 + g * gstep + (size_t)k0 * HPH);
        }
        #pragma unroll
        for (int ks = 0; ks < 32; ks += 16) {
            wmma::fragment<wmma::matrix_a, 16, 16, 16, __half, wmma::row_major> af;
            wmma::load_matrix_sync(af, &sH[cur][(wm * 16) * 40 + ks], 40);
            #pragma unroll
            for (int g = 0; g < 3; g++)
                #pragma unroll
                for (int p = 0; p < 2; p++) {
                    wmma::fragment<wmma::matrix_b, 16, 16, 16, __half, wmma::row_major> bfr;
                    wmma::load_matrix_sync(bfr, &sW[cur][(g * 32 + ks) * 72 + wn * 32 + p * 16], 72);
                    wmma::mma_sync(acc[g][p], af, bfr, acc[g][p]);
                }
        }
        if (it + 1 < NIT) {
            const int nxt = cur ^ 1;
            *(uint4*)&sH[nxt][hrow * 40 + hch] = hR;
            #pragma unroll
            for (int g = 0; g < 3; g++) *(uint4*)&sW[nxt][(g * 32 + wkr) * 72 + wch] = wR[g];
            __syncthreads();
        }
    }
    __syncthreads();   // repurpose smem as sC

    float* cw = &sCall[warp * 3 * 256];
    #pragma unroll
    for (int p = 0; p < 2; p++) {
        #pragma unroll
        for (int g = 0; g < 3; g++)
            wmma::store_matrix_sync(cw + g * 256, acc[g][p], 16, wmma::mem_row_major);
        __syncwarp();
        {
            const __half* xpr = (const __half*)&xPre[p][0];
            const __half* xpz = (const __half*)&xPre[p][1];
            const __half* xpn = (const __half*)&xPre[p][2];
            const float* hpr = hprev + (size_t)eb * HP;
            float* hor = hout + (size_t)eb * HP;
            __half* horh = houth + (size_t)eb * HPH;
            #pragma unroll
            for (int q = 0; q < 8; q++) {
                int e = erow * 16 + ec0 + q;
                int j = j0 + wn * 32 + p * 16 + ec0 + q;
                if (j < HH) {
                    float cr = cw[0 * 256 + e], cz = cw[1 * 256 + e], cn = cw[2 * 256 + e];
                    float r = 1.f / (1.f + __expf(-(__half2float(xpr[q]) + cr + bhh[j])));
                    float z = 1.f / (1.f + __expf(-(__half2float(xpz[q]) + cz + bhh[HH + j])));
                    float nn = tanhf(__half2float(xpn[q]) + r * (cn + bhh[2 * HH + j]));
                    float val = (1.f - z) * nn + z * hpr[j];
                    hor[j] = val;
                    horh[j] = H16(val);
                }
            }
        }
        __syncwarp();
    }
}

// =================== 3. word attention scores (fp16, double-buffered) ===================
__global__ __launch_bounds__(256, 2) void word_score3(
    const float* __restrict__ bw, const float* __restrict__ pw)
{
    __shared__ __half sA[2][64 * 40];
    __shared__ __half sB[2][32 * 136];
    __shared__ float  sC[8 * 256];
    __shared__ float  srow[64];

    const int t = blockIdx.x;
    const int b0 = blockIdx.y * 64;
    const int tid = threadIdx.x;
    const int warp = tid >> 5, lane = tid & 31;
    const int wm = warp >> 2, wn = warp & 3;

    const __half* hfh = g_hfh + (size_t)(t + 1) * BDIM * HPH;
    const __half* hrh = g_hrh + (size_t)t * BDIM * HPH;

    if (tid < 64) srow[tid] = 0.f;

    const int arow = tid >> 2, ach = (tid & 3) * 8;
    const __half* af_p = hfh + (size_t)(b0 + arow) * HPH + ach;
    const __half* ar_p = hrh + (size_t)(b0 + arow) * HPH + ach;
    const int bkr = tid >> 3, bch = (tid & 7) * 16;
    const int NIT = WKP / 32;  // 16

    for (int nc = 0; nc < 512; nc += 128) {
        wmma::fragment<wmma::accumulator, 16, 16, 16, float> acc[2][2];
        #pragma unroll
        for (int mi = 0; mi < 2; mi++)
            #pragma unroll
            for (int ni = 0; ni < 2; ni++) wmma::fill_fragment(acc[mi][ni], 0.f);

        uint4 aR = *(const uint4*)af_p;
        uint4 bR0 = *(const uint4*)&g_Ww[(size_t)bkr * WNP + nc + bch];
        uint4 bR1 = *(const uint4*)&g_Ww[(size_t)bkr * WNP + nc + bch + 8];

        __syncthreads();
        *(uint4*)&sA[0][arow * 40 + ach] = aR;
        *(uint4*)&sB[0][bkr * 136 + bch]     = bR0;
        *(uint4*)&sB[0][bkr * 136 + bch + 8] = bR1;
        __syncthreads();

        for (int it = 0; it < NIT; ++it) {
            const int cur = it & 1;
            if (it + 1 < NIT) {
                int k0 = (it + 1) * 32;
                aR = (k0 < HPH) ? *(const uint4*)(af_p + k0)
                                : *(const uint4*)(ar_p + (k0 - HPH));
                bR0 = *(const uint4*)&g_Ww[(size_t)(k0 + bkr) * WNP + nc + bch];
                bR1 = *(const uint4*)&g_Ww[(size_t)(k0 + bkr) * WNP + nc + bch + 8];
            }
            #pragma unroll
            for (int ks = 0; ks < 32; ks += 16) {
                wmma::fragment<wmma::matrix_a, 16, 16, 16, __half, wmma::row_major> af[2];
                #pragma unroll
                for (int mi = 0; mi < 2; mi++)
                    wmma::load_matrix_sync(af[mi], &sA[cur][(wm * 32 + mi * 16) * 40 + ks], 40);
                #pragma unroll
                for (int ni = 0; ni < 2; ni++) {
                    wmma::fragment<wmma::matrix_b, 16, 16, 16, __half, wmma::row_major> bfr;
                    wmma::load_matrix_sync(bfr, &sB[cur][ks * 136 + wn * 32 + ni * 16], 136);
                    #pragma unroll
                    for (int mi = 0; mi < 2; mi++)
                        wmma::mma_sync(acc[mi][ni], af[mi], bfr, acc[mi][ni]);
                }
            }
            if (it + 1 < NIT) {
                const int nxt = cur ^ 1;
                *(uint4*)&sA[nxt][arow * 40 + ach] = aR;
                *(uint4*)&sB[nxt][bkr * 136 + bch]     = bR0;
                *(uint4*)&sB[nxt][bkr * 136 + bch + 8] = bR1;
                __syncthreads();
            }
        }
        float* cw = &sC[warp * 256];
        #pragma unroll
        for (int mi = 0; mi < 2; mi++)
            #pragma unroll
            for (int ni = 0; ni < 2; ni++) {
                wmma::store_matrix_sync(cw, acc[mi][ni], 16, wmma::mem_row_major);
                __syncwarp();
                float part = 0.f;
                #pragma unroll
                for (int q = 0; q < 8; q++) {
                    int e = lane * 8 + q;
                    int col = e & 15;
                    int j = nc + wn * 32 + ni * 16 + col;
                    if (j < H2) part += tanhf(cw[e] + bw[j]) * pw[j];
                }
                atomicAdd(&srow[wm * 32 + mi * 16 + (lane >> 1)], part);
                __syncwarp();
            }
    }
    __syncthreads();
    if (tid < 64) g_scores[(size_t)(b0 + tid) * TT + t] = srow[tid];
}

// =================== 4. softmax + weighted sum, one warp per b, vectorized ===================
__global__ __launch_bounds__(256) void word_attn2()
{
    __shared__ float alpha[8][TT];
    const int tid = threadIdx.x;
    const int w = tid >> 5, lane = tid & 31;
    const int b = blockIdx.x * 8 + w;

    // warp-local softmax over 64 scores (2 per lane)
    float s0 = g_scores[(size_t)b * TT + lane];
    float s1 = g_scores[(size_t)b * TT + 32 + lane];
    float m = fmaxf(s0, s1);
    #pragma unroll
    for (int off = 16; off > 0; off >>= 1) m = fmaxf(m, __shfl_xor_sync(0xffffffffu, m, off));
    float e0 = __expf(s0 - m), e1 = __expf(s1 - m);
    float sum = e0 + e1;
    #pragma unroll
    for (int off = 16; off > 0; off >>= 1) sum += __shfl_xor_sync(0xffffffffu, sum, off);
    float inv = 1.f / sum;
    alpha[w][lane] = e0 * inv;
    alpha[w][32 + lane] = e1 * inv;
    __syncwarp();

    const size_t stride = (size_t)BDIM * HPH;
    if (lane < 29) {   // 29 uint4-chunks cover j in [0,232); pads are zero
        // forward h (slab t2+1) -> wordvec cols [0,230)
        {
            const __half* base = g_hfh + stride + (size_t)b * HPH + lane * 8;
            float acc[8] = {0.f, 0.f, 0.f, 0.f, 0.f, 0.f, 0.f, 0.f};
            for (int t2 = 0; t2 < TT; t2++) {
                uint4 hv = *(const uint4*)(base + (size_t)t2 * stride);
                const __half* hh = (const __half*)&hv;
                float a = alpha[w][t2];
                #pragma unroll
                for (int q = 0; q < 8; q++) acc[q] += a * __half2float(hh[q]);
            }
            #pragma unroll
            for (int q = 0; q < 8; q++) {
                int j = lane * 8 + q;
                if (j < HH) g_wordvec[(size_t)b * H2 + j] = acc[q];
            }
        }
        // reverse h (slab t2) -> wordvec cols [230,460)
        {
            const __half* base = g_hrh + (size_t)b * HPH + lane * 8;
            float acc[8] = {0.f, 0.f, 0.f, 0.f, 0.f, 0.f, 0.f, 0.f};
            for (int t2 = 0; t2 < TT; t2++) {
                uint4 hv = *(const uint4*)(base + (size_t)t2 * stride);
                const __half* hh = (const __half*)&hv;
                float a = alpha[w][t2];
                #pragma unroll
                for (int q = 0; q < 8; q++) acc[q] += a * __half2float(hh[q]);
            }
            #pragma unroll
            for (int q = 0; q < 8; q++) {
                int j = lane * 8 + q;
                if (j < HH) g_wordvec[(size_t)b * H2 + HH + j] = acc[q];
            }
        }
    }
}

// =================== 5. zero output ===================
__global__ void zero_out(float* __restrict__ out, int n)
{
    int i = blockIdx.x * 256 + threadIdx.x;
    if (i < n) out[i] = 0.f;
}

// =================== 6. sentence attention + FC + scatter ===================
__global__ void sent_kernel(const float* __restrict__ Wsent, const float* __restrict__ bsent,
                            const float* __restrict__ psent, const float* __restrict__ fcW,
                            const float* __restrict__ fcb, const int* __restrict__ pairs,
                            float* __restrict__ out)
{
    __shared__ float wvs[MS][H2];
    __shared__ float score[MS];
    __shared__ float beta[MS];
    __shared__ float sv[H2];
    const int nb = blockIdx.x;
    const int tid = threadIdx.x;

    for (int i = tid; i < MS * H2; i += 256)
        wvs[i / H2][i % H2] = g_wordvec[(size_t)nb * MS * H2 + i];
    if (tid < MS) score[tid] = 0.f;
    __syncthreads();

    for (int j = tid; j < H2; j += 256) {
        float acc[MS];
        #pragma unroll
        for (int s = 0; s < MS; s++) acc[s] = 0.f;
        for (int k = 0; k < H2; k++) {
            float w = Wsent[(size_t)k * H2 + j];
            #pragma unroll
            for (int s = 0; s < MS; s++) acc[s] += wvs[s][k] * w;
        }
        float bb = bsent[j], pp = psent[j];
        #pragma unroll
        for (int s = 0; s < MS; s++) atomicAdd(&score[s], tanhf(acc[s] + bb) * pp);
    }
    __syncthreads();
    if (tid == 0) {
        float m = -1e30f;
        for (int s = 0; s < MS; s++) m = fmaxf(m, score[s]);
        float sum = 0.f;
        for (int s = 0; s < MS; s++) { beta[s] = __expf(score[s] - m); sum += beta[s]; }
        float inv = 1.f / sum;
        for (int s = 0; s < MS; s++) beta[s] *= inv;
    }
    __syncthreads();
    for (int hcol = tid; hcol < H2; hcol += 256) {
        float acc = 0.f;
        #pragma unroll
        for (int s = 0; s < MS; s++) acc += beta[s] * wvs[s][hcol];
        sv[hcol] = acc;
    }
    __syncthreads();
    if (tid < NOUT) {
        int o = tid;
        float acc = fcb[o];
        for (int k = 0; k < H2; k++) acc += sv[k] * fcW[(size_t)o * H2 + k];
        int p0 = pairs[nb * 3 + 0];
        int p1 = pairs[nb * 3 + 1];
        int p2 = pairs[nb * 3 + 2];
        out[(((size_t)p0 * NENT + p1) * NENT + p2) * NOUT + o] = acc;
    }
}

// =================== launcher ===================
extern "C" void kernel_launch(void* const* d_in, const int* in_sizes, int n_in,
                              void* d_out, int out_size)
{
    const float* bag       = (const float*)d_in[0];
    const float* W_ih_f    = (const float*)d_in[1];
    const float* W_hh_f    = (const float*)d_in[2];
    const float* b_ih_f    = (const float*)d_in[3];
    const float* b_hh_f    = (const float*)d_in[4];
    const float* W_ih_r    = (const float*)d_in[5];
    const float* W_hh_r    = (const float*)d_in[6];
    const float* b_ih_r    = (const float*)d_in[7];
    const float* b_hh_r    = (const float*)d_in[8];
    const float* W_word    = (const float*)d_in[9];
    const float* b_word    = (const float*)d_in[10];
    const float* proj_word = (const float*)d_in[11];
    const float* W_sent    = (const float*)d_in[12];
    const float* b_sent    = (const float*)d_in[13];
    const float* proj_sent = (const float*)d_in[14];
    const float* fc_W      = (const float*)d_in[15];
    const float* fc_b      = (const float*)d_in[16];
    const int*   pairs     = (const int*)d_in[17];
    float* out = (float*)d_out;

    // 0. pre-convert operands to fp16 MMA-ready layouts
    {
        size_t nx = (size_t)M_TOT * 46;
        conv_x<<<(unsigned)((nx + 255) / 256), 256>>>(bag);
        int nwih = 2 * 361 * G3;
        conv_wih<<<(nwih + 255) / 256, 256>>>(W_ih_f, b_ih_f, W_ih_r, b_ih_r);
        int nwhh = 2 * 3 * HH * HH;
        conv_whh<<<(nwhh + 255) / 256, 256>>>(W_hh_f, W_hh_r);
        int nww = WKP * H2;
        conv_ww<<<(nww + 255) / 256, 256>>>(W_word);
    }

    // 1. input GEMMs (bias folded via ones-column), gate-padded xg layout
    dim3 gI(NXP / 128, M_TOT / 128, 2);
    input_gemm3<<<gI, 256>>>();

    // 2. 64 sequential GRU steps (fwd + rev concurrent per launch)
    dim3 gS(4, BDIM / 64, 2);
    for (int s = 0; s < TT; s++)
        gru_step3<<<gS, 256>>>(b_hh_f, b_hh_r, s);

    // 3. word attention scores
    dim3 gW(TT, BDIM / 64);
    word_score3<<<gW, 256>>>(b_word, proj_word);

    // 4. softmax over t + word_vec (one warp per b, vectorized)
    word_attn2<<<BDIM / 8, 256>>>();

    // 5. zero output buffer
    int n_out = NDOCS * NENT * NENT * NOUT;
    zero_out<<<(n_out + 255) / 256, 256>>>(out, n_out);

    // 6. sentence attention + FC + scatter
    sent_kernel<<<NBAG, 256>>>(W_sent, b_sent, proj_sent, fc_W, fc_b, pairs, out);
}